// round 16
// baseline (speedup 1.0000x reference)
#include <cuda_runtime.h>
#include <math.h>

#define Bz 32
#define Tz 512
#define Iz 256
#define Hz 1024
#define G4 4096
#define Oz 512
#define TR 500

typedef unsigned long long ull;

// ---- packed f32x2 helpers (sm_103a) ----
__device__ __forceinline__ ull pack2(float x, float y) {
    ull r; asm("mov.b64 %0, {%1,%2};" : "=l"(r) : "f"(x), "f"(y)); return r;
}
__device__ __forceinline__ void unpack2(ull v, float& x, float& y) {
    asm("mov.b64 {%0,%1}, %2;" : "=f"(x), "=f"(y) : "l"(v));
}
__device__ __forceinline__ void fma2(ull& d, ull a, ull b) {
    asm("fma.rn.f32x2 %0, %1, %2, %0;" : "+l"(d) : "l"(a), "l"(b));
}

__device__ __forceinline__ float sig_f(float x) {
    return __fdividef(1.0f, 1.0f + __expf(-x));
}
__device__ __forceinline__ float tanh_f(float x) {
    return 1.0f - __fdividef(2.0f, __expf(2.0f * x) + 1.0f);
}

// round-to-nearest tf32
__device__ __forceinline__ float t32(float x) {
    unsigned u; asm("cvt.rna.tf32.f32 %0, %1;" : "=r"(u) : "f"(x));
    return __uint_as_float(u);
}

// cp.async 16B: global -> shared (L2-only path)
__device__ __forceinline__ void cp16(unsigned smem_addr, const void* gptr) {
    asm volatile("cp.async.cg.shared.global [%0], [%1], 16;"
                 :: "r"(smem_addr), "l"(gptr) : "memory");
}

// mma.sync m16n8k8 tf32: D += A*B (accumulate in-place)
__device__ __forceinline__ void mma_tf32(float* c, const float* a, const float* b) {
    asm volatile(
        "mma.sync.aligned.m16n8k8.row.col.f32.tf32.tf32.f32 "
        "{%0,%1,%2,%3}, {%4,%5,%6,%7}, {%8,%9}, {%0,%1,%2,%3};"
        : "+f"(c[0]), "+f"(c[1]), "+f"(c[2]), "+f"(c[3])
        : "r"(__float_as_uint(a[0])), "r"(__float_as_uint(a[1])),
          "r"(__float_as_uint(a[2])), "r"(__float_as_uint(a[3])),
          "r"(__float_as_uint(b[0])), "r"(__float_as_uint(b[1])));
}

// ---- scratch (device globals: allocation-free) ----
__device__ __align__(16) float g_xt [Tz * Bz * Iz];
__device__ __align__(16) float g_xg [Tz * Bz * G4];
__device__ __align__(16) float g_h1r[Tz * Bz * Hz];    // layer0 h, tf32-rounded
__device__ __align__(16) float g_h2r[Tz * Bz * Hz];    // layer1 h, tf32-rounded
__device__ __align__(16) float g_h2 [Tz * Bz * Hz];    // layer1 h, full fp32 (FC)
__device__ __align__(16) float g_w0r[G4 * Iz];
__device__ __align__(16) float g_w1r[G4 * Hz];

// ---- hierarchical grid barrier (128 blocks = 16 arrivals x 8 sub-counters) ----
// Sub-counters 1KB apart -> distinct L2 lines/partitions: arrival atomics run
// in parallel (8 x 16x~30cyc) instead of 128 serialized on one address.
#define NSUB 8
#define SUBSTRIDE 256   // u32 units = 1KB spacing
__device__ __align__(128) unsigned g_sub[NSUB * SUBSTRIDE];  // zero-init
__device__ unsigned g_master = 0;
__device__ volatile unsigned g_gen = 0;

__device__ __forceinline__ void grid_sync(int bid) {
    __syncthreads();
    if (threadIdx.x == 0) {
        __threadfence();
        unsigned gen = g_gen;
        unsigned sub = ((unsigned)bid & (NSUB - 1)) * SUBSTRIDE;
        if (atomicAdd(&g_sub[sub], 1u) == 15u) {       // 16th arrival of this group
            g_sub[sub] = 0;                             // all 16 in; safe to reset
            __threadfence();
            if (atomicAdd(&g_master, 1u) == NSUB - 1u) {
                g_master = 0;
                __threadfence();
                g_gen = gen + 1u;
            }
        }
        while (g_gen == gen) { }
        __threadfence();
    }
    __syncthreads();
}

// ---------------------------------------------------------------------------
// Transpose x: [B,T,I] -> time-major [T,B,I], tf32-rounded
// ---------------------------------------------------------------------------
__global__ void transpose_x(const float4* __restrict__ x, float4* __restrict__ xt) {
    int idx = blockIdx.x * blockDim.x + threadIdx.x;   // < 1048576
    int i4 = idx & 63;
    int m  = idx >> 6;
    int t  = m >> 5;
    int b  = m & 31;
    float4 v = x[(b * Tz + t) * (Iz / 4) + i4];
    v.x = t32(v.x); v.y = t32(v.y); v.z = t32(v.z); v.w = t32(v.w);
    xt[idx] = v;
}

__global__ void round_tf32_k(const float4* __restrict__ in, float4* __restrict__ out, int n4) {
    int i = blockIdx.x * blockDim.x + threadIdx.x;
    if (i < n4) {
        float4 v = in[i];
        v.x = t32(v.x); v.y = t32(v.y); v.z = t32(v.z); v.w = t32(v.w);
        out[i] = v;
    }
}

// ---------------------------------------------------------------------------
// TF32 tensor-core GEMM (TN) — R12 (passing). BM=BN=128, BK=32, 8 warps.
// ---------------------------------------------------------------------------
#define GST 36
#define TILE_F (128 * GST)

__global__ __launch_bounds__(256, 2)
void gemm_tf32(const float* __restrict__ A, const float* __restrict__ W,
               const float* __restrict__ b1, const float* __restrict__ b2,
               float* __restrict__ C, int M, int N, int K) {
    extern __shared__ float smg[];

    const int tid = threadIdx.x;
    const int lane = tid & 31;
    const int wid = tid >> 5;
    const int g = lane >> 2, tg = lane & 3;
    const int wm = wid & 1, wn = wid >> 1;
    const int m0 = blockIdx.y * 128, n0 = blockIdx.x * 128;

    unsigned smem_u32;
    asm("{ .reg .u64 t0; cvta.to.shared.u64 t0, %1; cvt.u32.u64 %0, t0; }"
        : "=r"(smem_u32) : "l"(smg));

    const int srow0 = tid >> 3, sc4 = tid & 7;
    const float* Abase = A + (size_t)m0 * K;
    const float* Wbase = W + (size_t)n0 * K;

    float acc[4][4][4];
#pragma unroll
    for (int mt = 0; mt < 4; mt++)
#pragma unroll
        for (int nt = 0; nt < 4; nt++)
#pragma unroll
            for (int i = 0; i < 4; i++) acc[mt][nt][i] = 0.0f;

    const int KT = K >> 5;

    auto issue = [&](int s, int kt) {
        unsigned sA = smem_u32 + (unsigned)(s * 2 * TILE_F) * 4u;
        unsigned sB = sA + (unsigned)TILE_F * 4u;
        const float* Ak = Abase + kt * 32;
        const float* Wk = Wbase + kt * 32;
#pragma unroll
        for (int i = 0; i < 4; i++) {
            int row = srow0 + 32 * i;
            unsigned doff = (unsigned)(row * GST + sc4 * 4) * 4u;
            cp16(sA + doff, Ak + (size_t)row * K + sc4 * 4);
            cp16(sB + doff, Wk + (size_t)row * K + sc4 * 4);
        }
    };

    issue(0, 0);
    asm volatile("cp.async.commit_group;" ::: "memory");
    issue(1, 1);
    asm volatile("cp.async.commit_group;" ::: "memory");

    for (int kt = 0; kt < KT; kt++) {
        asm volatile("cp.async.wait_group 1;" ::: "memory");
        __syncthreads();

        const int s = kt & 1;
        const float* sa = smg + s * 2 * TILE_F + (wm * 64) * GST;
        const float* sb = smg + s * 2 * TILE_F + TILE_F + (wn * 32) * GST;

#pragma unroll
        for (int ks = 0; ks < 4; ks++) {
            const int kk = ks * 8;
            float a[4][4], b[4][2];
#pragma unroll
            for (int mt = 0; mt < 4; mt++) {
                const float* ap = sa + (mt * 16) * GST + kk;
                a[mt][0] = ap[g * GST + tg];
                a[mt][1] = ap[(g + 8) * GST + tg];
                a[mt][2] = ap[g * GST + tg + 4];
                a[mt][3] = ap[(g + 8) * GST + tg + 4];
            }
#pragma unroll
            for (int nt = 0; nt < 4; nt++) {
                const float* bp = sb + (nt * 8) * GST + kk;
                b[nt][0] = bp[g * GST + tg];
                b[nt][1] = bp[g * GST + tg + 4];
            }
#pragma unroll
            for (int mt = 0; mt < 4; mt++)
#pragma unroll
                for (int nt = 0; nt < 4; nt++)
                    mma_tf32(acc[mt][nt], a[mt], b[nt]);
        }
        __syncthreads();
        if (kt + 2 < KT) issue(s, kt + 2);
        asm volatile("cp.async.commit_group;" ::: "memory");
    }

#pragma unroll
    for (int nt = 0; nt < 4; nt++) {
        int col = n0 + wn * 32 + nt * 8 + 2 * tg;
        float bia0 = b1[col]     + (b2 ? b2[col]     : 0.0f);
        float bia1 = b1[col + 1] + (b2 ? b2[col + 1] : 0.0f);
#pragma unroll
        for (int mt = 0; mt < 4; mt++) {
            int row = m0 + wm * 64 + mt * 16 + g;
            float2 v0 = make_float2(acc[mt][nt][0] + bia0, acc[mt][nt][1] + bia1);
            float2 v1 = make_float2(acc[mt][nt][2] + bia0, acc[mt][nt][3] + bia1);
            *(float2*)(C + (size_t)row * N + col) = v0;
            *(float2*)(C + (size_t)(row + 8) * N + col) = v1;
        }
    }
}

// ---------------------------------------------------------------------------
// SGEMM (TN) f32x2 — FC layer (full precision on the output path)
// ---------------------------------------------------------------------------
__global__ __launch_bounds__(256, 2)
void sgemm_fc(const float* __restrict__ A, const float* __restrict__ W,
              const float* __restrict__ b1,
              float* __restrict__ C, int M, int N, int K) {
    __shared__ __align__(16) float As[16][128];
    __shared__ __align__(16) float Bs[16][128];

    const int tid = threadIdx.x;
    const int ty = tid >> 4, tx = tid & 15;
    const int m0 = blockIdx.y * 128, n0 = blockIdx.x * 128;

    ull acc[4][8];
#pragma unroll
    for (int i = 0; i < 4; i++)
#pragma unroll
        for (int j = 0; j < 8; j++) acc[i][j] = 0ULL;

    const float* arow[2];
    int arr[2], acc4[2];
#pragma unroll
    for (int i = 0; i < 2; i++) {
        int item = tid + 256 * i;
        int r = item >> 2, c4 = item & 3;
        arr[i] = r; acc4[i] = c4;
        int m = m0 + r;
        int bb = m / TR, t = m - bb * TR;
        arow[i] = A + (long long)(t * Bz + bb) * K;
    }
    const float* wrow[2];
#pragma unroll
    for (int i = 0; i < 2; i++) wrow[i] = W + (long long)(n0 + arr[i]) * K;

    float4 va[2], vb[2];
#pragma unroll
    for (int i = 0; i < 2; i++) {
        va[i] = *(const float4*)(arow[i] + acc4[i] * 4);
        vb[i] = *(const float4*)(wrow[i] + acc4[i] * 4);
    }
#pragma unroll
    for (int i = 0; i < 2; i++) {
        int r = arr[i], c4 = acc4[i];
        As[c4 * 4 + 0][r] = va[i].x; As[c4 * 4 + 1][r] = va[i].y;
        As[c4 * 4 + 2][r] = va[i].z; As[c4 * 4 + 3][r] = va[i].w;
        Bs[c4 * 4 + 0][r] = vb[i].x; Bs[c4 * 4 + 1][r] = vb[i].y;
        Bs[c4 * 4 + 2][r] = vb[i].z; Bs[c4 * 4 + 3][r] = vb[i].w;
    }
    __syncthreads();

    const int KT = K >> 4;
    for (int kt = 0; kt < KT; kt++) {
        if (kt + 1 < KT) {
            int k0n = (kt + 1) << 4;
#pragma unroll
            for (int i = 0; i < 2; i++) {
                va[i] = *(const float4*)(arow[i] + k0n + acc4[i] * 4);
                vb[i] = *(const float4*)(wrow[i] + k0n + acc4[i] * 4);
            }
        }
#pragma unroll
        for (int k = 0; k < 16; k++) {
            ull a2[4];
#pragma unroll
            for (int mp = 0; mp < 4; mp++)
                a2[mp] = *(const ull*)&As[k][ty * 8 + mp * 2];
            float4 bv0 = *(const float4*)&Bs[k][tx * 8];
            float4 bv1 = *(const float4*)&Bs[k][tx * 8 + 4];
            ull bd[8];
            bd[0] = pack2(bv0.x, bv0.x); bd[1] = pack2(bv0.y, bv0.y);
            bd[2] = pack2(bv0.z, bv0.z); bd[3] = pack2(bv0.w, bv0.w);
            bd[4] = pack2(bv1.x, bv1.x); bd[5] = pack2(bv1.y, bv1.y);
            bd[6] = pack2(bv1.z, bv1.z); bd[7] = pack2(bv1.w, bv1.w);
#pragma unroll
            for (int mp = 0; mp < 4; mp++)
#pragma unroll
                for (int n = 0; n < 8; n++) fma2(acc[mp][n], a2[mp], bd[n]);
        }
        if (kt + 1 < KT) {
            __syncthreads();
#pragma unroll
            for (int i = 0; i < 2; i++) {
                int r = arr[i], c4 = acc4[i];
                As[c4 * 4 + 0][r] = va[i].x; As[c4 * 4 + 1][r] = va[i].y;
                As[c4 * 4 + 2][r] = va[i].z; As[c4 * 4 + 3][r] = va[i].w;
                Bs[c4 * 4 + 0][r] = vb[i].x; Bs[c4 * 4 + 1][r] = vb[i].y;
                Bs[c4 * 4 + 2][r] = vb[i].z; Bs[c4 * 4 + 3][r] = vb[i].w;
            }
            __syncthreads();
        }
    }

    float bb[8];
#pragma unroll
    for (int n = 0; n < 8; n++) bb[n] = b1[n0 + tx * 8 + n];
#pragma unroll
    for (int mp = 0; mp < 4; mp++) {
        float lo[8], hi[8];
#pragma unroll
        for (int n = 0; n < 8; n++) unpack2(acc[mp][n], lo[n], hi[n]);
        int row0 = m0 + ty * 8 + mp * 2;
        float* c0 = C + (long long)row0 * N + n0 + tx * 8;
        float* c1 = c0 + N;
        float o0[8], o1[8];
#pragma unroll
        for (int n = 0; n < 8; n++) { o0[n] = lo[n] + bb[n]; o1[n] = hi[n] + bb[n]; }
        *(float4*)(c0)     = make_float4(o0[0], o0[1], o0[2], o0[3]);
        *(float4*)(c0 + 4) = make_float4(o0[4], o0[5], o0[6], o0[7]);
        *(float4*)(c1)     = make_float4(o1[0], o1[1], o1[2], o1[3]);
        *(float4*)(c1 + 4) = make_float4(o1[4], o1[5], o1[6], o1[7]);
    }
}

// ---------------------------------------------------------------------------
// R15: tensor-core persistent LSTM recurrence (R14 math, cheaper sync).
// - hierarchical grid barrier (see above)
// - xg for step t+1 prefetched BEFORE the barrier spin (latency hidden)
// - final step's barrier skipped (uniform; nothing in-kernel consumes h[T-1])
// ---------------------------------------------------------------------------
#define HST2 516     // h smem row stride (516%32==4 -> (4g+tg)%32 conflict-free)

__global__ __launch_bounds__(256, 1)
void lstm_rec_tc(const float* __restrict__ xg,    // [T][B][4H]
                 const float* __restrict__ Whh,   // [4H][H] fp32
                 float* __restrict__ hr,          // [T][B][H] tf32-rounded out
                 float* __restrict__ hf) {        // [T][B][H] fp32 out (nullable)
    extern __shared__ float sm[];
    float* hsm = sm;                         // [2][32][HST2]
    float* gsm = sm + 2 * 32 * HST2;         // [4][32][34]

    const int tid = threadIdx.x;
    const int lane = tid & 31, wid = tid >> 5;
    const int wm = wid & 1, wk = wid >> 1;   // wm: gate-row tile, wk: k-quarter
    const int g = lane >> 2, tg = lane & 3;
    const int bid = blockIdx.x;
    const int j0 = bid * 8;
    const int eu = tid & 7, eb = tid >> 3;   // epilogue role: (batch eb, unit eu)
    const int j = j0 + eu;

    unsigned hsm_u32;
    asm("{ .reg .u64 t0; cvta.to.shared.u64 t0, %1; cvt.u32.u64 %0, t0; }"
        : "=r"(hsm_u32) : "l"(hsm));

    // ---- W A-fragments -> registers (once per layer), tf32-rounded.
    float wa[2][16][4];
    {
        const float* r0 = Whh + (size_t)((wm * 2)     * Hz + j0 + g) * Hz;
        const float* r1 = Whh + (size_t)((wm * 2 + 1) * Hz + j0 + g) * Hz;
#pragma unroll
        for (int half = 0; half < 2; half++)
#pragma unroll
            for (int kt = 0; kt < 16; kt++) {
                int k = half * 512 + wk * 128 + kt * 8;
                wa[half][kt][0] = t32(__ldg(r0 + k + tg));
                wa[half][kt][1] = t32(__ldg(r1 + k + tg));
                wa[half][kt][2] = t32(__ldg(r0 + k + tg + 4));
                wa[half][kt][3] = t32(__ldg(r1 + k + tg + 4));
            }
    }

    // stage one k-half of h[t-1]: 32 rows x 512 floats = 4096 cp16, 16/thread
    auto stage = [&](int half, const float* hp) {
#pragma unroll
        for (int i = 0; i < 16; i++) {
            int idx = i * 256 + tid;
            int row = idx >> 7, ch = idx & 127;
            cp16(hsm_u32 + (unsigned)((half * 32 + row) * HST2 + ch * 4) * 4u,
                 hp + (size_t)row * Hz + half * 512 + ch * 4);
        }
        asm volatile("cp.async.commit_group;" ::: "memory");
    };

    float creg = 0.0f;   // c[eb][j] register-resident

    // prefetch xg for t = 0
    float pi, pf, pg, po;
    {
        const float* xr = xg + (size_t)eb * G4;
        pi = __ldg(xr + j);
        pf = __ldg(xr + Hz + j);
        pg = __ldg(xr + 2 * Hz + j);
        po = __ldg(xr + 3 * Hz + j);
    }

    for (int t = 0; t < Tz; t++) {
        if (t > 0) {
            const float* hp = hr + (size_t)(t - 1) * Bz * Hz;
            stage(0, hp);
            stage(1, hp);

            float acc[4][4];
#pragma unroll
            for (int nt = 0; nt < 4; nt++)
#pragma unroll
                for (int i = 0; i < 4; i++) acc[nt][i] = 0.0f;

#pragma unroll
            for (int half = 0; half < 2; half++) {
                if (half == 0) asm volatile("cp.async.wait_group 1;" ::: "memory");
                else           asm volatile("cp.async.wait_group 0;" ::: "memory");
                __syncthreads();
                const float* hb = hsm + half * 32 * HST2 + wk * 128;
#pragma unroll
                for (int kt = 0; kt < 16; kt++) {
                    const int kc = kt * 8;
#pragma unroll
                    for (int nt = 0; nt < 4; nt++) {
                        float b[2];
                        const float* bp = hb + (nt * 8 + g) * HST2 + kc;
                        b[0] = bp[tg];
                        b[1] = bp[tg + 4];
                        mma_tf32(acc[nt], wa[half][kt], b);
                    }
                }
            }

            // publish wk-partials: gsm[wk][gate-row][batch], stride 34
            float* gp = gsm + wk * (32 * 34);
#pragma unroll
            for (int nt = 0; nt < 4; nt++) {
                int bcol = nt * 8 + 2 * tg;
                *(float2*)(gp + (wm * 16 + g) * 34 + bcol) =
                    make_float2(acc[nt][0], acc[nt][1]);
                *(float2*)(gp + (wm * 16 + 8 + g) * 34 + bcol) =
                    make_float2(acc[nt][2], acc[nt][3]);
            }
            __syncthreads();

            // gather gates for (eb, eu): row = gate*8+eu, sum 4 wk partials
#pragma unroll
            for (int gt = 0; gt < 4; gt++) {
                int row = gt * 8 + eu;
                float s = gsm[row * 34 + eb]
                        + gsm[1 * 32 * 34 + row * 34 + eb]
                        + gsm[2 * 32 * 34 + row * 34 + eb]
                        + gsm[3 * 32 * 34 + row * 34 + eb];
                if      (gt == 0) pi += s;
                else if (gt == 1) pf += s;
                else if (gt == 2) pg += s;
                else              po += s;
            }
        }

        float si = sig_f(pi);
        float sf = sig_f(pf);
        float so = sig_f(po);
        creg = sf * creg + si * tanh_f(pg);
        float hn = so * tanh_f(creg);
        size_t oidx = (size_t)t * Bz * Hz + (size_t)eb * Hz + j;
        if (hf) hf[oidx] = hn;
        hr[oidx] = t32(hn);

        if (t + 1 < Tz) {
            // prefetch next step's xg BEFORE the barrier spin (independent of h)
            const float* xr = xg + (size_t)(t + 1) * Bz * G4 + (size_t)eb * G4;
            pi = __ldg(xr + j);
            pf = __ldg(xr + Hz + j);
            pg = __ldg(xr + 2 * Hz + j);
            po = __ldg(xr + 3 * Hz + j);
            grid_sync(bid);
        }
    }
}

// ---------------------------------------------------------------------------
extern "C" void kernel_launch(void* const* d_in, const int* in_sizes, int n_in,
                              void* d_out, int out_size) {
    (void)in_sizes; (void)n_in; (void)out_size;
    const float* x     = (const float*)d_in[0];
    const float* W_ih0 = (const float*)d_in[1];
    const float* W_hh0 = (const float*)d_in[2];
    const float* b_ih0 = (const float*)d_in[3];
    const float* b_hh0 = (const float*)d_in[4];
    const float* W_ih1 = (const float*)d_in[5];
    const float* W_hh1 = (const float*)d_in[6];
    const float* b_ih1 = (const float*)d_in[7];
    const float* b_hh1 = (const float*)d_in[8];
    const float* W_fc  = (const float*)d_in[9];
    const float* b_fc  = (const float*)d_in[10];
    float* out = (float*)d_out;

    float *xt, *xgp, *h1r, *h2r, *h2, *w0r, *w1r;
    cudaGetSymbolAddress((void**)&xt,  g_xt);
    cudaGetSymbolAddress((void**)&xgp, g_xg);
    cudaGetSymbolAddress((void**)&h1r, g_h1r);
    cudaGetSymbolAddress((void**)&h2r, g_h2r);
    cudaGetSymbolAddress((void**)&h2,  g_h2);
    cudaGetSymbolAddress((void**)&w0r, g_w0r);
    cudaGetSymbolAddress((void**)&w1r, g_w1r);

    const int REC_SMEM  = (2 * 32 * HST2 + 4 * 32 * 34) * (int)sizeof(float); // 149504B
    const int GEMM_SMEM = 2 * 2 * TILE_F * (int)sizeof(float);                // 73728B
    cudaFuncSetAttribute(lstm_rec_tc,
                         cudaFuncAttributeMaxDynamicSharedMemorySize, REC_SMEM);
    cudaFuncSetAttribute(gemm_tf32,
                         cudaFuncAttributeMaxDynamicSharedMemorySize, GEMM_SMEM);

    // x -> time-major (tf32); round input-GEMM weights
    transpose_x<<<4096, 256>>>((const float4*)x, (float4*)xt);
    round_tf32_k<<<(G4 * Iz / 4 + 255) / 256, 256>>>((const float4*)W_ih0, (float4*)w0r, G4 * Iz / 4);
    round_tf32_k<<<(G4 * Hz / 4 + 255) / 256, 256>>>((const float4*)W_ih1, (float4*)w1r, G4 * Hz / 4);

    // layer 0: tf32 input GEMM + tensor-core recurrence (writes h1r tf32)
    gemm_tf32<<<dim3(G4 / 128, (Tz * Bz) / 128), 256, GEMM_SMEM>>>(
        xt, w0r, b_ih0, b_hh0, xgp, Tz * Bz, G4, Iz);
    lstm_rec_tc<<<128, 256, REC_SMEM>>>(xgp, W_hh0, h1r, nullptr);

    // layer 1: tf32 input GEMM (A = h1r, already rounded) + recurrence
    gemm_tf32<<<dim3(G4 / 128, (Tz * Bz) / 128), 256, GEMM_SMEM>>>(
        h1r, w1r, b_ih1, b_hh1, xgp, Tz * Bz, G4, Hz);
    lstm_rec_tc<<<128, 256, REC_SMEM>>>(xgp, W_hh1, h2r, h2);

    // FC over truncated sequence (full fp32): out[b,t,o], m = b*500 + t
    sgemm_fc<<<dim3(Oz / 128, (Bz * TR) / 128), 256>>>(h2, W_fc, b_fc,
                                                       out, Bz * TR, Oz, Hz);
}

// round 17
// speedup vs baseline: 1.1068x; 1.1068x over previous
#include <cuda_runtime.h>
#include <math.h>

#define Bz 32
#define Tz 512
#define Iz 256
#define Hz 1024
#define G4 4096
#define Oz 512
#define TR 500

typedef unsigned long long ull;

// ---- packed f32x2 helpers (sm_103a) ----
__device__ __forceinline__ ull pack2(float x, float y) {
    ull r; asm("mov.b64 %0, {%1,%2};" : "=l"(r) : "f"(x), "f"(y)); return r;
}
__device__ __forceinline__ void unpack2(ull v, float& x, float& y) {
    asm("mov.b64 {%0,%1}, %2;" : "=f"(x), "=f"(y) : "l"(v));
}
__device__ __forceinline__ void fma2(ull& d, ull a, ull b) {
    asm("fma.rn.f32x2 %0, %1, %2, %0;" : "+l"(d) : "l"(a), "l"(b));
}

__device__ __forceinline__ float sig_f(float x) {
    return __fdividef(1.0f, 1.0f + __expf(-x));
}
__device__ __forceinline__ float tanh_f(float x) {
    return 1.0f - __fdividef(2.0f, __expf(2.0f * x) + 1.0f);
}

// round-to-nearest tf32
__device__ __forceinline__ float t32(float x) {
    unsigned u; asm("cvt.rna.tf32.f32 %0, %1;" : "=r"(u) : "f"(x));
    return __uint_as_float(u);
}

// cp.async 16B: global -> shared (L2-only path)
__device__ __forceinline__ void cp16(unsigned smem_addr, const void* gptr) {
    asm volatile("cp.async.cg.shared.global [%0], [%1], 16;"
                 :: "r"(smem_addr), "l"(gptr) : "memory");
}

// mma.sync m16n8k8 tf32: D += A*B (accumulate in-place)
__device__ __forceinline__ void mma_tf32(float* c, const float* a, const float* b) {
    asm volatile(
        "mma.sync.aligned.m16n8k8.row.col.f32.tf32.tf32.f32 "
        "{%0,%1,%2,%3}, {%4,%5,%6,%7}, {%8,%9}, {%0,%1,%2,%3};"
        : "+f"(c[0]), "+f"(c[1]), "+f"(c[2]), "+f"(c[3])
        : "r"(__float_as_uint(a[0])), "r"(__float_as_uint(a[1])),
          "r"(__float_as_uint(a[2])), "r"(__float_as_uint(a[3])),
          "r"(__float_as_uint(b[0])), "r"(__float_as_uint(b[1])));
}

// ---- scratch (device globals: allocation-free) ----
__device__ __align__(16) float g_xt [Tz * Bz * Iz];
__device__ __align__(16) float g_xg [Tz * Bz * G4];
__device__ __align__(16) float g_h1r[Tz * Bz * Hz];    // layer0 h, tf32-rounded
__device__ __align__(16) float g_h2r[Tz * Bz * Hz];    // layer1 h, tf32-rounded
__device__ __align__(16) float g_h2 [Tz * Bz * Hz];    // layer1 h, full fp32 (FC)
__device__ __align__(16) float g_w0r[G4 * Iz];
__device__ __align__(16) float g_w1r[G4 * Hz];

// ---- flat software grid barrier (R14-proven: arrivals overlap block skew) ----
__device__ unsigned g_bar_count = 0;
__device__ volatile unsigned g_bar_gen = 0;

__device__ __forceinline__ void grid_sync() {
    __syncthreads();
    if (threadIdx.x == 0) {
        __threadfence();
        unsigned gen = g_bar_gen;
        if (atomicAdd(&g_bar_count, 1u) == gridDim.x - 1u) {
            g_bar_count = 0;
            __threadfence();
            g_bar_gen = gen + 1u;
        } else {
            while (g_bar_gen == gen) { }
            __threadfence();
        }
    }
    __syncthreads();
}

// ---------------------------------------------------------------------------
// Transpose x: [B,T,I] -> time-major [T,B,I], tf32-rounded
// ---------------------------------------------------------------------------
__global__ void transpose_x(const float4* __restrict__ x, float4* __restrict__ xt) {
    int idx = blockIdx.x * blockDim.x + threadIdx.x;   // < 1048576
    int i4 = idx & 63;
    int m  = idx >> 6;
    int t  = m >> 5;
    int b  = m & 31;
    float4 v = x[(b * Tz + t) * (Iz / 4) + i4];
    v.x = t32(v.x); v.y = t32(v.y); v.z = t32(v.z); v.w = t32(v.w);
    xt[idx] = v;
}

__global__ void round_tf32_k(const float4* __restrict__ in, float4* __restrict__ out, int n4) {
    int i = blockIdx.x * blockDim.x + threadIdx.x;
    if (i < n4) {
        float4 v = in[i];
        v.x = t32(v.x); v.y = t32(v.y); v.z = t32(v.z); v.w = t32(v.w);
        out[i] = v;
    }
}

// ---------------------------------------------------------------------------
// TF32 tensor-core GEMM (TN) — R12 (passing). BM=BN=128, BK=32, 8 warps.
// ---------------------------------------------------------------------------
#define GST 36
#define TILE_F (128 * GST)

__global__ __launch_bounds__(256, 2)
void gemm_tf32(const float* __restrict__ A, const float* __restrict__ W,
               const float* __restrict__ b1, const float* __restrict__ b2,
               float* __restrict__ C, int M, int N, int K) {
    extern __shared__ float smg[];

    const int tid = threadIdx.x;
    const int lane = tid & 31;
    const int wid = tid >> 5;
    const int g = lane >> 2, tg = lane & 3;
    const int wm = wid & 1, wn = wid >> 1;
    const int m0 = blockIdx.y * 128, n0 = blockIdx.x * 128;

    unsigned smem_u32;
    asm("{ .reg .u64 t0; cvta.to.shared.u64 t0, %1; cvt.u32.u64 %0, t0; }"
        : "=r"(smem_u32) : "l"(smg));

    const int srow0 = tid >> 3, sc4 = tid & 7;
    const float* Abase = A + (size_t)m0 * K;
    const float* Wbase = W + (size_t)n0 * K;

    float acc[4][4][4];
#pragma unroll
    for (int mt = 0; mt < 4; mt++)
#pragma unroll
        for (int nt = 0; nt < 4; nt++)
#pragma unroll
            for (int i = 0; i < 4; i++) acc[mt][nt][i] = 0.0f;

    const int KT = K >> 5;

    auto issue = [&](int s, int kt) {
        unsigned sA = smem_u32 + (unsigned)(s * 2 * TILE_F) * 4u;
        unsigned sB = sA + (unsigned)TILE_F * 4u;
        const float* Ak = Abase + kt * 32;
        const float* Wk = Wbase + kt * 32;
#pragma unroll
        for (int i = 0; i < 4; i++) {
            int row = srow0 + 32 * i;
            unsigned doff = (unsigned)(row * GST + sc4 * 4) * 4u;
            cp16(sA + doff, Ak + (size_t)row * K + sc4 * 4);
            cp16(sB + doff, Wk + (size_t)row * K + sc4 * 4);
        }
    };

    issue(0, 0);
    asm volatile("cp.async.commit_group;" ::: "memory");
    issue(1, 1);
    asm volatile("cp.async.commit_group;" ::: "memory");

    for (int kt = 0; kt < KT; kt++) {
        asm volatile("cp.async.wait_group 1;" ::: "memory");
        __syncthreads();

        const int s = kt & 1;
        const float* sa = smg + s * 2 * TILE_F + (wm * 64) * GST;
        const float* sb = smg + s * 2 * TILE_F + TILE_F + (wn * 32) * GST;

#pragma unroll
        for (int ks = 0; ks < 4; ks++) {
            const int kk = ks * 8;
            float a[4][4], b[4][2];
#pragma unroll
            for (int mt = 0; mt < 4; mt++) {
                const float* ap = sa + (mt * 16) * GST + kk;
                a[mt][0] = ap[g * GST + tg];
                a[mt][1] = ap[(g + 8) * GST + tg];
                a[mt][2] = ap[g * GST + tg + 4];
                a[mt][3] = ap[(g + 8) * GST + tg + 4];
            }
#pragma unroll
            for (int nt = 0; nt < 4; nt++) {
                const float* bp = sb + (nt * 8) * GST + kk;
                b[nt][0] = bp[g * GST + tg];
                b[nt][1] = bp[g * GST + tg + 4];
            }
#pragma unroll
            for (int mt = 0; mt < 4; mt++)
#pragma unroll
                for (int nt = 0; nt < 4; nt++)
                    mma_tf32(acc[mt][nt], a[mt], b[nt]);
        }
        __syncthreads();
        if (kt + 2 < KT) issue(s, kt + 2);
        asm volatile("cp.async.commit_group;" ::: "memory");
    }

#pragma unroll
    for (int nt = 0; nt < 4; nt++) {
        int col = n0 + wn * 32 + nt * 8 + 2 * tg;
        float bia0 = b1[col]     + (b2 ? b2[col]     : 0.0f);
        float bia1 = b1[col + 1] + (b2 ? b2[col + 1] : 0.0f);
#pragma unroll
        for (int mt = 0; mt < 4; mt++) {
            int row = m0 + wm * 64 + mt * 16 + g;
            float2 v0 = make_float2(acc[mt][nt][0] + bia0, acc[mt][nt][1] + bia1);
            float2 v1 = make_float2(acc[mt][nt][2] + bia0, acc[mt][nt][3] + bia1);
            *(float2*)(C + (size_t)row * N + col) = v0;
            *(float2*)(C + (size_t)(row + 8) * N + col) = v1;
        }
    }
}

// ---------------------------------------------------------------------------
// SGEMM (TN) f32x2 — FC layer (full precision on the output path)
// ---------------------------------------------------------------------------
__global__ __launch_bounds__(256, 2)
void sgemm_fc(const float* __restrict__ A, const float* __restrict__ W,
              const float* __restrict__ b1,
              float* __restrict__ C, int M, int N, int K) {
    __shared__ __align__(16) float As[16][128];
    __shared__ __align__(16) float Bs[16][128];

    const int tid = threadIdx.x;
    const int ty = tid >> 4, tx = tid & 15;
    const int m0 = blockIdx.y * 128, n0 = blockIdx.x * 128;

    ull acc[4][8];
#pragma unroll
    for (int i = 0; i < 4; i++)
#pragma unroll
        for (int j = 0; j < 8; j++) acc[i][j] = 0ULL;

    const float* arow[2];
    int arr[2], acc4[2];
#pragma unroll
    for (int i = 0; i < 2; i++) {
        int item = tid + 256 * i;
        int r = item >> 2, c4 = item & 3;
        arr[i] = r; acc4[i] = c4;
        int m = m0 + r;
        int bb = m / TR, t = m - bb * TR;
        arow[i] = A + (long long)(t * Bz + bb) * K;
    }
    const float* wrow[2];
#pragma unroll
    for (int i = 0; i < 2; i++) wrow[i] = W + (long long)(n0 + arr[i]) * K;

    float4 va[2], vb[2];
#pragma unroll
    for (int i = 0; i < 2; i++) {
        va[i] = *(const float4*)(arow[i] + acc4[i] * 4);
        vb[i] = *(const float4*)(wrow[i] + acc4[i] * 4);
    }
#pragma unroll
    for (int i = 0; i < 2; i++) {
        int r = arr[i], c4 = acc4[i];
        As[c4 * 4 + 0][r] = va[i].x; As[c4 * 4 + 1][r] = va[i].y;
        As[c4 * 4 + 2][r] = va[i].z; As[c4 * 4 + 3][r] = va[i].w;
        Bs[c4 * 4 + 0][r] = vb[i].x; Bs[c4 * 4 + 1][r] = vb[i].y;
        Bs[c4 * 4 + 2][r] = vb[i].z; Bs[c4 * 4 + 3][r] = vb[i].w;
    }
    __syncthreads();

    const int KT = K >> 4;
    for (int kt = 0; kt < KT; kt++) {
        if (kt + 1 < KT) {
            int k0n = (kt + 1) << 4;
#pragma unroll
            for (int i = 0; i < 2; i++) {
                va[i] = *(const float4*)(arow[i] + k0n + acc4[i] * 4);
                vb[i] = *(const float4*)(wrow[i] + k0n + acc4[i] * 4);
            }
        }
#pragma unroll
        for (int k = 0; k < 16; k++) {
            ull a2[4];
#pragma unroll
            for (int mp = 0; mp < 4; mp++)
                a2[mp] = *(const ull*)&As[k][ty * 8 + mp * 2];
            float4 bv0 = *(const float4*)&Bs[k][tx * 8];
            float4 bv1 = *(const float4*)&Bs[k][tx * 8 + 4];
            ull bd[8];
            bd[0] = pack2(bv0.x, bv0.x); bd[1] = pack2(bv0.y, bv0.y);
            bd[2] = pack2(bv0.z, bv0.z); bd[3] = pack2(bv0.w, bv0.w);
            bd[4] = pack2(bv1.x, bv1.x); bd[5] = pack2(bv1.y, bv1.y);
            bd[6] = pack2(bv1.z, bv1.z); bd[7] = pack2(bv1.w, bv1.w);
#pragma unroll
            for (int mp = 0; mp < 4; mp++)
#pragma unroll
                for (int n = 0; n < 8; n++) fma2(acc[mp][n], a2[mp], bd[n]);
        }
        if (kt + 1 < KT) {
            __syncthreads();
#pragma unroll
            for (int i = 0; i < 2; i++) {
                int r = arr[i], c4 = acc4[i];
                As[c4 * 4 + 0][r] = va[i].x; As[c4 * 4 + 1][r] = va[i].y;
                As[c4 * 4 + 2][r] = va[i].z; As[c4 * 4 + 3][r] = va[i].w;
                Bs[c4 * 4 + 0][r] = vb[i].x; Bs[c4 * 4 + 1][r] = vb[i].y;
                Bs[c4 * 4 + 2][r] = vb[i].z; Bs[c4 * 4 + 3][r] = vb[i].w;
            }
            __syncthreads();
        }
    }

    float bb[8];
#pragma unroll
    for (int n = 0; n < 8; n++) bb[n] = b1[n0 + tx * 8 + n];
#pragma unroll
    for (int mp = 0; mp < 4; mp++) {
        float lo[8], hi[8];
#pragma unroll
        for (int n = 0; n < 8; n++) unpack2(acc[mp][n], lo[n], hi[n]);
        int row0 = m0 + ty * 8 + mp * 2;
        float* c0 = C + (long long)row0 * N + n0 + tx * 8;
        float* c1 = c0 + N;
        float o0[8], o1[8];
#pragma unroll
        for (int n = 0; n < 8; n++) { o0[n] = lo[n] + bb[n]; o1[n] = hi[n] + bb[n]; }
        *(float4*)(c0)     = make_float4(o0[0], o0[1], o0[2], o0[3]);
        *(float4*)(c0 + 4) = make_float4(o0[4], o0[5], o0[6], o0[7]);
        *(float4*)(c1)     = make_float4(o1[0], o1[1], o1[2], o1[3]);
        *(float4*)(c1 + 4) = make_float4(o1[4], o1[5], o1[6], o1[7]);
    }
}

// ---------------------------------------------------------------------------
// R16: tensor-core persistent LSTM recurrence = R14 (proven 7.82ms) with two
// safe deltas only: (1) xg[t+1] prefetched before the barrier spin; (2) final
// step's barrier skipped. Flat grid barrier restored (R15's hierarchical tree
// deepened the critical path and regressed).
// ---------------------------------------------------------------------------
#define HST2 516     // h smem row stride (516%32==4 -> (4g+tg)%32 conflict-free)

__global__ __launch_bounds__(256, 1)
void lstm_rec_tc(const float* __restrict__ xg,    // [T][B][4H]
                 const float* __restrict__ Whh,   // [4H][H] fp32
                 float* __restrict__ hr,          // [T][B][H] tf32-rounded out
                 float* __restrict__ hf) {        // [T][B][H] fp32 out (nullable)
    extern __shared__ float sm[];
    float* hsm = sm;                         // [2][32][HST2]
    float* gsm = sm + 2 * 32 * HST2;         // [4][32][34]

    const int tid = threadIdx.x;
    const int lane = tid & 31, wid = tid >> 5;
    const int wm = wid & 1, wk = wid >> 1;   // wm: gate-row tile, wk: k-quarter
    const int g = lane >> 2, tg = lane & 3;
    const int j0 = blockIdx.x * 8;
    const int eu = tid & 7, eb = tid >> 3;   // epilogue role: (batch eb, unit eu)
    const int j = j0 + eu;

    unsigned hsm_u32;
    asm("{ .reg .u64 t0; cvta.to.shared.u64 t0, %1; cvt.u32.u64 %0, t0; }"
        : "=r"(hsm_u32) : "l"(hsm));

    // ---- W A-fragments -> registers (once per layer), tf32-rounded.
    // m = wm*16 + (g | g+8): gate = wm*2 (+1 for g+8 row), unit = g.
    float wa[2][16][4];
    {
        const float* r0 = Whh + (size_t)((wm * 2)     * Hz + j0 + g) * Hz;
        const float* r1 = Whh + (size_t)((wm * 2 + 1) * Hz + j0 + g) * Hz;
#pragma unroll
        for (int half = 0; half < 2; half++)
#pragma unroll
            for (int kt = 0; kt < 16; kt++) {
                int k = half * 512 + wk * 128 + kt * 8;
                wa[half][kt][0] = t32(__ldg(r0 + k + tg));
                wa[half][kt][1] = t32(__ldg(r1 + k + tg));
                wa[half][kt][2] = t32(__ldg(r0 + k + tg + 4));
                wa[half][kt][3] = t32(__ldg(r1 + k + tg + 4));
            }
    }

    // stage one k-half of h[t-1]: 32 rows x 512 floats = 4096 cp16, 16/thread
    auto stage = [&](int half, const float* hp) {
#pragma unroll
        for (int i = 0; i < 16; i++) {
            int idx = i * 256 + tid;
            int row = idx >> 7, ch = idx & 127;
            cp16(hsm_u32 + (unsigned)((half * 32 + row) * HST2 + ch * 4) * 4u,
                 hp + (size_t)row * Hz + half * 512 + ch * 4);
        }
        asm volatile("cp.async.commit_group;" ::: "memory");
    };

    float creg = 0.0f;   // c[eb][j] register-resident

    // prefetch xg for t = 0
    float pi, pf, pg, po;
    {
        const float* xr = xg + (size_t)eb * G4;
        pi = __ldg(xr + j);
        pf = __ldg(xr + Hz + j);
        pg = __ldg(xr + 2 * Hz + j);
        po = __ldg(xr + 3 * Hz + j);
    }

    for (int t = 0; t < Tz; t++) {
        if (t > 0) {
            const float* hp = hr + (size_t)(t - 1) * Bz * Hz;
            stage(0, hp);
            stage(1, hp);

            float acc[4][4];
#pragma unroll
            for (int nt = 0; nt < 4; nt++)
#pragma unroll
                for (int i = 0; i < 4; i++) acc[nt][i] = 0.0f;

#pragma unroll
            for (int half = 0; half < 2; half++) {
                if (half == 0) asm volatile("cp.async.wait_group 1;" ::: "memory");
                else           asm volatile("cp.async.wait_group 0;" ::: "memory");
                __syncthreads();
                const float* hb = hsm + half * 32 * HST2 + wk * 128;
#pragma unroll
                for (int kt = 0; kt < 16; kt++) {
                    const int kc = kt * 8;
#pragma unroll
                    for (int nt = 0; nt < 4; nt++) {
                        float b[2];
                        const float* bp = hb + (nt * 8 + g) * HST2 + kc;
                        b[0] = bp[tg];
                        b[1] = bp[tg + 4];
                        mma_tf32(acc[nt], wa[half][kt], b);
                    }
                }
            }

            // publish wk-partials: gsm[wk][gate-row][batch], stride 34
            float* gp = gsm + wk * (32 * 34);
#pragma unroll
            for (int nt = 0; nt < 4; nt++) {
                int bcol = nt * 8 + 2 * tg;
                *(float2*)(gp + (wm * 16 + g) * 34 + bcol) =
                    make_float2(acc[nt][0], acc[nt][1]);
                *(float2*)(gp + (wm * 16 + 8 + g) * 34 + bcol) =
                    make_float2(acc[nt][2], acc[nt][3]);
            }
            __syncthreads();

            // gather gates for (eb, eu): row = gate*8+eu, sum 4 wk partials
#pragma unroll
            for (int gt = 0; gt < 4; gt++) {
                int row = gt * 8 + eu;
                float s = gsm[row * 34 + eb]
                        + gsm[1 * 32 * 34 + row * 34 + eb]
                        + gsm[2 * 32 * 34 + row * 34 + eb]
                        + gsm[3 * 32 * 34 + row * 34 + eb];
                if      (gt == 0) pi += s;
                else if (gt == 1) pf += s;
                else if (gt == 2) pg += s;
                else              po += s;
            }
        }

        float si = sig_f(pi);
        float sf = sig_f(pf);
        float so = sig_f(po);
        creg = sf * creg + si * tanh_f(pg);
        float hn = so * tanh_f(creg);
        size_t oidx = (size_t)t * Bz * Hz + (size_t)eb * Hz + j;
        if (hf) hf[oidx] = hn;
        hr[oidx] = t32(hn);

        if (t + 1 < Tz) {
            // prefetch next step's xg BEFORE the barrier spin (independent of h)
            const float* xr = xg + (size_t)(t + 1) * Bz * G4 + (size_t)eb * G4;
            pi = __ldg(xr + j);
            pf = __ldg(xr + Hz + j);
            pg = __ldg(xr + 2 * Hz + j);
            po = __ldg(xr + 3 * Hz + j);
            grid_sync();
        }
    }
}

// ---------------------------------------------------------------------------
extern "C" void kernel_launch(void* const* d_in, const int* in_sizes, int n_in,
                              void* d_out, int out_size) {
    (void)in_sizes; (void)n_in; (void)out_size;
    const float* x     = (const float*)d_in[0];
    const float* W_ih0 = (const float*)d_in[1];
    const float* W_hh0 = (const float*)d_in[2];
    const float* b_ih0 = (const float*)d_in[3];
    const float* b_hh0 = (const float*)d_in[4];
    const float* W_ih1 = (const float*)d_in[5];
    const float* W_hh1 = (const float*)d_in[6];
    const float* b_ih1 = (const float*)d_in[7];
    const float* b_hh1 = (const float*)d_in[8];
    const float* W_fc  = (const float*)d_in[9];
    const float* b_fc  = (const float*)d_in[10];
    float* out = (float*)d_out;

    float *xt, *xgp, *h1r, *h2r, *h2, *w0r, *w1r;
    cudaGetSymbolAddress((void**)&xt,  g_xt);
    cudaGetSymbolAddress((void**)&xgp, g_xg);
    cudaGetSymbolAddress((void**)&h1r, g_h1r);
    cudaGetSymbolAddress((void**)&h2r, g_h2r);
    cudaGetSymbolAddress((void**)&h2,  g_h2);
    cudaGetSymbolAddress((void**)&w0r, g_w0r);
    cudaGetSymbolAddress((void**)&w1r, g_w1r);

    const int REC_SMEM  = (2 * 32 * HST2 + 4 * 32 * 34) * (int)sizeof(float); // 149504B
    const int GEMM_SMEM = 2 * 2 * TILE_F * (int)sizeof(float);                // 73728B
    cudaFuncSetAttribute(lstm_rec_tc,
                         cudaFuncAttributeMaxDynamicSharedMemorySize, REC_SMEM);
    cudaFuncSetAttribute(gemm_tf32,
                         cudaFuncAttributeMaxDynamicSharedMemorySize, GEMM_SMEM);

    // x -> time-major (tf32); round input-GEMM weights
    transpose_x<<<4096, 256>>>((const float4*)x, (float4*)xt);
    round_tf32_k<<<(G4 * Iz / 4 + 255) / 256, 256>>>((const float4*)W_ih0, (float4*)w0r, G4 * Iz / 4);
    round_tf32_k<<<(G4 * Hz / 4 + 255) / 256, 256>>>((const float4*)W_ih1, (float4*)w1r, G4 * Hz / 4);

    // layer 0: tf32 input GEMM + tensor-core recurrence (writes h1r tf32)
    gemm_tf32<<<dim3(G4 / 128, (Tz * Bz) / 128), 256, GEMM_SMEM>>>(
        xt, w0r, b_ih0, b_hh0, xgp, Tz * Bz, G4, Iz);
    lstm_rec_tc<<<128, 256, REC_SMEM>>>(xgp, W_hh0, h1r, nullptr);

    // layer 1: tf32 input GEMM (A = h1r, already rounded) + recurrence
    gemm_tf32<<<dim3(G4 / 128, (Tz * Bz) / 128), 256, GEMM_SMEM>>>(
        h1r, w1r, b_ih1, b_hh1, xgp, Tz * Bz, G4, Hz);
    lstm_rec_tc<<<128, 256, REC_SMEM>>>(xgp, W_hh1, h2r, h2);

    // FC over truncated sequence (full fp32): out[b,t,o], m = b*500 + t
    sgemm_fc<<<dim3(Oz / 128, (Bz * TR) / 128), 256>>>(h2, W_fc, b_fc,
                                                       out, Bz * TR, Oz, Hz);
}